// round 17
// baseline (speedup 1.0000x reference)
#include <cuda_runtime.h>
#include <cuda_bf16.h>
#include <cstdint>

#define ULL unsigned long long

static constexpr int Bsz   = 2048;
static constexpr int T     = 512;
static constexpr int CHT   = 16;         // steps per chunk
static constexpr int NCH   = T / CHT;    // 32 chunks
static constexpr int NPROD = 128;        // producer CTAs (512 warps, 4 batches each)
static constexpr int NCONS = 512;        // consumer CTAs (4 warps, 1 batch each)

// pre-packed Wx B-fragments (bf16 hi/lo) + bias pairs
__device__ uint2  g_Bh[4][8][32];
__device__ uint2  g_Bl[4][8][32];
__device__ float2 g_bias[8][4];
// z scratch [b][t][gate] + ready flags [b][chunk]
__device__ float  g_z[(size_t)Bsz * T * 64];
__device__ int    g_rdy[Bsz * NCH];

// ---------------- helpers ----------------
__device__ __forceinline__ ULL f2pack(float lo, float hi) {
    ULL r; asm("mov.b64 %0, {%1, %2};" : "=l"(r) : "f"(lo), "f"(hi)); return r;
}
__device__ __forceinline__ void f2unpack(ULL v, float& lo, float& hi) {
    asm("mov.b64 {%0, %1}, %2;" : "=f"(lo), "=f"(hi) : "l"(v));
}
__device__ __forceinline__ ULL ffma2(ULL a, ULL b, ULL c) {
    ULL d; asm("fma.rn.f32x2 %0, %1, %2, %3;" : "=l"(d) : "l"(a), "l"(b), "l"(c)); return d;
}
__device__ __forceinline__ ULL fadd2(ULL a, ULL b) {
    ULL d; asm("add.rn.f32x2 %0, %1, %2;" : "=l"(d) : "l"(a), "l"(b)); return d;
}
__device__ __forceinline__ float fast_sigmoid(float x) {
    float e, r;
    asm("ex2.approx.f32 %0, %1;" : "=f"(e) : "f"(x * -1.4426950408889634f));
    asm("rcp.approx.f32 %0, %1;" : "=f"(r) : "f"(1.0f + e));
    return r;
}
__device__ __forceinline__ uint32_t bf16x2_hi(float x0, float x1) {
    uint32_t r; asm("cvt.rn.bf16x2.f32 %0, %1, %2;" : "=r"(r) : "f"(x1), "f"(x0)); return r;
}
__device__ __forceinline__ uint32_t bf16x2_lo(float x0, float x1, uint32_t hi) {
    float h0 = __uint_as_float(hi << 16);
    float h1 = __uint_as_float(hi & 0xFFFF0000u);
    return bf16x2_hi(x0 - h0, x1 - h1);
}
__device__ __forceinline__ void mma16816(float* c, const uint32_t* a, const uint32_t* b) {
    asm("mma.sync.aligned.m16n8k16.row.col.f32.bf16.bf16.f32 "
        "{%0,%1,%2,%3}, {%4,%5,%6,%7}, {%8,%9}, {%0,%1,%2,%3};"
        : "+f"(c[0]), "+f"(c[1]), "+f"(c[2]), "+f"(c[3])
        : "r"(a[0]), "r"(a[1]), "r"(a[2]), "r"(a[3]), "r"(b[0]), "r"(b[1]));
}
__device__ __forceinline__ int ld_acquire(const int* p) {
    int v; asm volatile("ld.acquire.gpu.global.s32 %0, [%1];" : "=r"(v) : "l"(p) : "memory");
    return v;
}
__device__ __forceinline__ void st_release(int* p, int v) {
    asm volatile("st.release.gpu.global.s32 [%0], %1;" :: "l"(p), "r"(v) : "memory");
}

// ============================================================================
// prep: pack Wx into bf16 hi/lo B-fragments + bias pairs
// ============================================================================
__global__ void prep_kernel(const float* __restrict__ Wx, const float* __restrict__ bias) {
    const int tid  = threadIdx.x;
    const int ks   = tid >> 5;
    const int lane = tid & 31;
    const int gr   = lane >> 2;
    const int tq   = (lane & 3) * 2;
    const int k0   = ks * 16 + tq;
#pragma unroll
    for (int nt = 0; nt < 8; nt++) {
        const int n = nt * 8 + gr;
        float w00 = Wx[(k0)     * 64 + n], w01 = Wx[(k0 + 1) * 64 + n];
        float w10 = Wx[(k0 + 8) * 64 + n], w11 = Wx[(k0 + 9) * 64 + n];
        uint32_t h0 = bf16x2_hi(w00, w01);
        uint32_t h1 = bf16x2_hi(w10, w11);
        g_Bh[ks][nt][lane] = make_uint2(h0, h1);
        g_Bl[ks][nt][lane] = make_uint2(bf16x2_lo(w00, w01, h0), bf16x2_lo(w10, w11, h1));
    }
    if (tid < 32) {
        int nt = tid >> 2, q = tid & 3;
        g_bias[nt][q] = make_float2(bias[nt * 8 + 2 * q], bias[nt * 8 + 2 * q + 1]);
    }
}

// ============================================================================
// Decoupled producer/consumer LSTM.
//  CTAs [0, NPROD): producers — warp owns 4 batches; per chunk writes the
//    16x64 z tile (HMMA, 6-chain ILP) to g_z and release-publishes a flag.
//  CTAs [NPROD, NPROD+NCONS): consumers — warp owns 1 batch; acquires the
//    chunk flag, then runs the R5-validated recurrence chain (z prefetch x4).
// No inter-CTA barriers; producers never wait -> deadlock-free.
// ============================================================================
__global__ void __launch_bounds__(128, 5)
lstm_pc(const float* __restrict__ x,
        const float* __restrict__ Wh,   // [16, 64]
        const float* __restrict__ W2, const float* __restrict__ b2,
        const float* __restrict__ W3, const float* __restrict__ b3,
        const float* __restrict__ Wo, const float* __restrict__ bo,
        float* __restrict__ out)
{
    const int lane = threadIdx.x & 31;
    const int w    = threadIdx.x >> 5;

    if (blockIdx.x < NPROD) {
        // ========================= PRODUCER =========================
        const int pw = blockIdx.x * 4 + w;      // 0..511; batches 4pw..4pw+3
        const int r  = lane >> 2;
        const int cq = (lane & 3) * 2;

#pragma unroll 1
        for (int c = 0; c < NCH; c++) {
#pragma unroll 1
            for (int i = 0; i < 4; i++) {
                const int b = pw * 4 + i;
                const float* xc = x + ((size_t)b * T + c * CHT) * 64;

                uint32_t ah[4][4], al[4][4];
#pragma unroll
                for (int ks = 0; ks < 4; ks++) {
                    const int k0 = ks * 16 + cq;
                    float2 a0 = __ldg((const float2*)(xc + (r)     * 64 + k0));
                    float2 a1 = __ldg((const float2*)(xc + (r + 8) * 64 + k0));
                    float2 a2 = __ldg((const float2*)(xc + (r)     * 64 + k0 + 8));
                    float2 a3 = __ldg((const float2*)(xc + (r + 8) * 64 + k0 + 8));
                    ah[ks][0] = bf16x2_hi(a0.x, a0.y); al[ks][0] = bf16x2_lo(a0.x, a0.y, ah[ks][0]);
                    ah[ks][1] = bf16x2_hi(a1.x, a1.y); al[ks][1] = bf16x2_lo(a1.x, a1.y, ah[ks][1]);
                    ah[ks][2] = bf16x2_hi(a2.x, a2.y); al[ks][2] = bf16x2_lo(a2.x, a2.y, ah[ks][2]);
                    ah[ks][3] = bf16x2_hi(a3.x, a3.y); al[ks][3] = bf16x2_lo(a3.x, a3.y, ah[ks][3]);
                }

                float* zc = g_z + ((size_t)b * T + c * CHT) * 64;
#pragma unroll
                for (int np = 0; np < 4; np++) {
                    const int n0 = 2 * np, n1 = 2 * np + 1;
                    float c0h[4] = {0,0,0,0}, c0l[4] = {0,0,0,0}, c0x[4] = {0,0,0,0};
                    float c1h[4] = {0,0,0,0}, c1l[4] = {0,0,0,0}, c1x[4] = {0,0,0,0};
#pragma unroll
                    for (int ks = 0; ks < 4; ks++) {
                        uint2 bh0 = __ldg(&g_Bh[ks][n0][lane]);
                        uint2 bl0 = __ldg(&g_Bl[ks][n0][lane]);
                        uint2 bh1 = __ldg(&g_Bh[ks][n1][lane]);
                        uint2 bl1 = __ldg(&g_Bl[ks][n1][lane]);
                        mma16816(c0h, ah[ks], &bh0.x);
                        mma16816(c0l, ah[ks], &bl0.x);
                        mma16816(c0x, al[ks], &bh0.x);
                        mma16816(c1h, ah[ks], &bh1.x);
                        mma16816(c1l, ah[ks], &bl1.x);
                        mma16816(c1x, al[ks], &bh1.x);
                    }
                    float2 bs0 = __ldg(&g_bias[n0][cq >> 1]);
                    float2 bs1 = __ldg(&g_bias[n1][cq >> 1]);
                    *(float2*)(zc + (r)     * 64 + n0 * 8 + cq) =
                        make_float2(c0h[0] + c0l[0] + c0x[0] + bs0.x,
                                    c0h[1] + c0l[1] + c0x[1] + bs0.y);
                    *(float2*)(zc + (r + 8) * 64 + n0 * 8 + cq) =
                        make_float2(c0h[2] + c0l[2] + c0x[2] + bs0.x,
                                    c0h[3] + c0l[3] + c0x[3] + bs0.y);
                    *(float2*)(zc + (r)     * 64 + n1 * 8 + cq) =
                        make_float2(c1h[0] + c1l[0] + c1x[0] + bs1.x,
                                    c1h[1] + c1l[1] + c1x[1] + bs1.y);
                    *(float2*)(zc + (r + 8) * 64 + n1 * 8 + cq) =
                        make_float2(c1h[2] + c1l[2] + c1x[2] + bs1.x,
                                    c1h[3] + c1l[3] + c1x[3] + bs1.y);
                }
                __syncwarp();
                if (lane == 0) {
                    __threadfence();
                    st_release(&g_rdy[b * NCH + c], 1);
                }
                __syncwarp();
            }
        }
    } else {
        // ========================= CONSUMER =========================
        const int b = (blockIdx.x - NPROD) * 4 + w;
        __shared__ __align__(16) float sh[4][32];

        ULL wha[8], whb[8];
#pragma unroll
        for (int kk = 0; kk < 8; kk++) {
            wha[kk] = f2pack(__ldg(&Wh[(2 * kk) * 64 + lane]),
                             __ldg(&Wh[(2 * kk + 1) * 64 + lane]));
            whb[kk] = f2pack(__ldg(&Wh[(2 * kk) * 64 + lane + 32]),
                             __ldg(&Wh[(2 * kk + 1) * 64 + lane + 32]));
        }
        sh[w][lane] = 0.0f;
        float c_state = 0.0f;
        const ulonglong2* hv = (const ulonglong2*)sh[w];
        const float* zb = g_z + (size_t)b * T * 64;
        const int* fbase = &g_rdy[b * NCH];
        __syncwarp();

#pragma unroll 1
        for (int c = 0; c < NCH; c++) {
            if (ld_acquire(fbase + c) == 0) {
                while (ld_acquire(fbase + c) == 0) __nanosleep(64);
            }
            const float* zc = zb + (size_t)c * CHT * 64;
            float zA[4], zB[4];
#pragma unroll
            for (int j = 0; j < 4; j++) {
                zA[j] = zc[j * 64 + lane];
                zB[j] = zc[j * 64 + lane + 32];
            }
#pragma unroll
            for (int tl = 0; tl < CHT; tl++) {
                ULL hp[8];
                {
                    ulonglong2 v0 = hv[0], v1 = hv[1], v2 = hv[2], v3 = hv[3];
                    hp[0] = v0.x; hp[1] = v0.y; hp[2] = v1.x; hp[3] = v1.y;
                    hp[4] = v2.x; hp[5] = v2.y; hp[6] = v3.x; hp[7] = v3.y;
                }
                ULL aa0 = f2pack(zA[tl & 3], 0.0f), aa1 = 0ULL;
                ULL ab0 = f2pack(zB[tl & 3], 0.0f), ab1 = 0ULL;
#pragma unroll
                for (int kk = 0; kk < 8; kk++) {
                    if (kk & 1) { aa1 = ffma2(hp[kk], wha[kk], aa1); ab1 = ffma2(hp[kk], whb[kk], ab1); }
                    else        { aa0 = ffma2(hp[kk], wha[kk], aa0); ab0 = ffma2(hp[kk], whb[kk], ab0); }
                }
                ULL sa = fadd2(aa0, aa1), sb = fadd2(ab0, ab1);
                float a0, a1, b0f, b1f;
                f2unpack(sa, a0, a1);
                f2unpack(sb, b0f, b1f);
                float za  = a0 + a1;    // lane<16: i | lane>=16: f
                float zbv = b0f + b1f;  // lane<16: g | lane>=16: o

                float v1 = fast_sigmoid(za);
                float v2 = (lane < 16) ? fmaxf(zbv, 0.0f) : fast_sigmoid(zbv);

                float fpart = __shfl_xor_sync(0xFFFFFFFFu, v1, 16);
                float opart = __shfl_xor_sync(0xFFFFFFFFu, v2, 16);

                c_state = fpart * c_state + v1 * v2;      // valid lanes 0..15
                float hnew = opart * fmaxf(c_state, 0.0f);
                sh[w][lane] = hnew;
                __syncwarp();

                if (tl + 4 < CHT) {                       // rolling z prefetch
                    zA[tl & 3] = zc[(tl + 4) * 64 + lane];
                    zB[tl & 3] = zc[(tl + 4) * 64 + lane + 32];
                }
            }
        }

        // ---- MLP head: lane 0 per consumer warp ----
        if (lane == 0) {
            const float* hT = sh[w];
            float x2v[8];
#pragma unroll
            for (int u = 0; u < 8; u++) {
                float s = __ldg(&b2[u]);
#pragma unroll
                for (int j = 0; j < 16; j++) s += hT[j] * __ldg(&W2[j * 8 + u]);
                x2v[u] = fmaxf(s, 0.0f);
            }
            float x3v[4];
#pragma unroll
            for (int u = 0; u < 4; u++) {
                float s = __ldg(&b3[u]);
#pragma unroll
                for (int j = 0; j < 8; j++) s += x2v[j] * __ldg(&W3[j * 4 + u]);
                x3v[u] = fmaxf(s, 0.0f);
            }
            float s = __ldg(&bo[0]);
#pragma unroll
            for (int u = 0; u < 4; u++) s += x3v[u] * __ldg(&Wo[u]);
            out[b] = fast_sigmoid(s);
        }
    }
}

extern "C" void kernel_launch(void* const* d_in, const int* in_sizes, int n_in,
                              void* d_out, int out_size) {
    (void)in_sizes; (void)n_in; (void)out_size;
    const float* x  = (const float*)d_in[0];
    const float* Wx = (const float*)d_in[1];
    const float* Wh = (const float*)d_in[2];
    const float* b  = (const float*)d_in[3];
    const float* W2 = (const float*)d_in[4];
    const float* b2 = (const float*)d_in[5];
    const float* W3 = (const float*)d_in[6];
    const float* b3 = (const float*)d_in[7];
    const float* Wo = (const float*)d_in[8];
    const float* bo = (const float*)d_in[9];
    float* out = (float*)d_out;

    // reset ready flags (graph-capturable async memset), then pack weights,
    // then the decoupled producer/consumer kernel.
    void* rdy_ptr = nullptr;
    cudaGetSymbolAddress(&rdy_ptr, g_rdy);
    cudaMemsetAsync(rdy_ptr, 0, sizeof(int) * Bsz * NCH);
    prep_kernel<<<1, 128>>>(Wx, b);
    lstm_pc<<<NPROD + NCONS, 128>>>(x, Wh, W2, b2, W3, b3, Wo, bo, out);
}